// round 11
// baseline (speedup 1.0000x reference)
#include <cuda_runtime.h>
#include <cuda_fp16.h>
#include <cstdint>

#define MMV 2048
#define NNV 4096
#define KKV 4096
#define TOT_ITERS (1024 * 64)   // 32x32 tiles of 64x128, 64 k-iters each

// Scratch (__device__ globals; no allocations allowed)
__device__ __align__(16) __half g_xh[(size_t)MMV * KKV];  // fp16(x)
__device__ __align__(16) __half g_wd[(size_t)KKV * NNV];  // fp16(s*(q-z)), [K][N]

// ---------------------------------------------------------------------------
// asm helpers
// ---------------------------------------------------------------------------
__device__ __forceinline__ void ldsm4(uint32_t* r, uint32_t addr) {
    asm volatile("ldmatrix.sync.aligned.m8n8.x4.shared.b16 {%0,%1,%2,%3}, [%4];"
                 : "=r"(r[0]), "=r"(r[1]), "=r"(r[2]), "=r"(r[3]) : "r"(addr));
}
__device__ __forceinline__ void ldsm4t(uint32_t* r, uint32_t addr) {
    asm volatile("ldmatrix.sync.aligned.m8n8.x4.trans.shared.b16 {%0,%1,%2,%3}, [%4];"
                 : "=r"(r[0]), "=r"(r[1]), "=r"(r[2]), "=r"(r[3]) : "r"(addr));
}
__device__ __forceinline__ void mma_f16(float* c, const uint32_t* a, const uint32_t* b) {
    asm volatile("mma.sync.aligned.m16n8k16.row.col.f32.f16.f16.f32 "
                 "{%0,%1,%2,%3}, {%4,%5,%6,%7}, {%8,%9}, {%0,%1,%2,%3};"
                 : "+f"(c[0]), "+f"(c[1]), "+f"(c[2]), "+f"(c[3])
                 : "r"(a[0]), "r"(a[1]), "r"(a[2]), "r"(a[3]), "r"(b[0]), "r"(b[1]));
}
__device__ __forceinline__ void cpa16(uint32_t s, const void* g) {
    asm volatile("cp.async.cg.shared.global [%0], [%1], 16;" :: "r"(s), "l"(g));
}
#define CP_COMMIT() asm volatile("cp.async.commit_group;" ::: "memory")
#define CP_WAIT1()  asm volatile("cp.async.wait_group 1;" ::: "memory")

// ---------------------------------------------------------------------------
// Fused prep (same as R9/R10): x->fp16; W unpack to fp16(s*(q-z))
// ---------------------------------------------------------------------------
__global__ void prep_kernel(const float4* __restrict__ x4,
                            const int* __restrict__ qw,
                            const float* __restrict__ zp,
                            const float* __restrict__ scales)
{
    if (blockIdx.x < 8192) {
        size_t i = (size_t)blockIdx.x * blockDim.x + threadIdx.x;   // over M*K/4
        float4 v = x4[i];
        __align__(8) __half h[4];
        h[0] = __float2half_rn(v.x); h[1] = __float2half_rn(v.y);
        h[2] = __float2half_rn(v.z); h[3] = __float2half_rn(v.w);
        ((uint2*)g_xh)[i] = *(uint2*)h;
    } else {
        int T = (blockIdx.x - 8192) * blockDim.x + threadIdx.x;     // < 512*2048
        int np = T & (NNV / 2 - 1);
        int kp = T >> 11;
        int g  = kp >> 4;
        int n0 = np * 2;
        float z0 = fminf(fmaxf(rintf(zp[g * NNV + n0]),     0.0f), 15.0f);
        float z1 = fminf(fmaxf(rintf(zp[g * NNV + n0 + 1]), 0.0f), 15.0f);
        float s0 = fminf(fmaxf(scales[g * NNV + n0],     1e-5f), 1e4f);
        float s1 = fminf(fmaxf(scales[g * NNV + n0 + 1], 1e-5f), 1e4f);
        int q0 = qw[(size_t)kp * NNV + n0];
        int q1 = qw[(size_t)kp * NNV + n0 + 1];
#pragma unroll
        for (int j = 0; j < 8; ++j) {
            float w0 = (float)((q0 >> (4 * j)) & 15);
            float w1 = (float)((q1 >> (4 * j)) & 15);
            __half2 o = __floats2half2_rn((w0 - z0) * s0, (w1 - z1) * s1);
            *(__half2*)(g_wd + (size_t)(kp * 8 + j) * NNV + n0) = o;
        }
    }
}

// ---------------------------------------------------------------------------
// Stream-K GEMM: C = xh @ Wd + bias (C pre-zeroed for atomic partials).
// Tile 64x128, BK=64, 4 warps (2m x 2n), warp tile 32x64 — R9 microkernel.
// Persistent grid = 3*numSM CTAs; each handles an equal contiguous span of
// the 65536 global k-iterations. Full tiles -> plain store (+bias); boundary
// tiles -> fp32 atomicAdd partials (+bias from the k0==0 contributor).
// ---------------------------------------------------------------------------
#define NS 3
#define STG_BYTES 24576
#define SMEM_TOTAL (NS * STG_BYTES)   // 73728

__global__ void __launch_bounds__(128, 3)
gemm_kernel(const float* __restrict__ bias,
            float* __restrict__ C,
            int q, int r)
{
    extern __shared__ __align__(16) char smem[];
    const uint32_t sb = (uint32_t)__cvta_generic_to_shared(smem);
    const int tid = threadIdx.x, lane = tid & 31, wid = tid >> 5;
    const int wm = wid & 1, wn = wid >> 1;

    const int cta   = blockIdx.x;
    const int start = cta * q + min(cta, r);
    const int end   = start + q + (cta < r ? 1 : 0);

    // loader: A 64x64 fp16 (512 x 16B chunks), B 64x128 fp16 (1024 chunks)
    auto load_stage = [&](int m0, int n0, int kt, int st) {
        uint32_t base = sb + st * STG_BYTES;
#pragma unroll
        for (int j = 0; j < 4; ++j) {
            int p = tid + j * 128;
            int rr = p >> 3, c = p & 7;
            uint32_t so = base + (uint32_t)(rr * 8 + (c ^ (rr & 7))) * 16;
            cpa16(so, g_xh + (size_t)(m0 + rr) * KKV + kt * 64 + c * 8);
        }
#pragma unroll
        for (int j = 0; j < 8; ++j) {
            int p = tid + j * 128;
            int rr = p >> 4, c = p & 15;
            uint32_t so = base + 8192 + (uint32_t)(rr * 16 + (c ^ (rr & 7))) * 16;
            cpa16(so, g_wd + (size_t)(kt * 64 + rr) * NNV + n0 + c * 8);
        }
    };

    // ldmatrix address precompute (tile-independent)
    const int lane_r = lane & 15, chh = lane >> 4;
    uint32_t arow[2], axr[2];
#pragma unroll
    for (int t = 0; t < 2; ++t) {
        int rr = wm * 32 + t * 16 + lane_r;
        arow[t] = (uint32_t)rr * 128;
        axr[t]  = (uint32_t)(rr & 7);
    }
    const uint32_t xb = (uint32_t)(lane_r & 7);
    uint32_t bcol[4];
#pragma unroll
    for (int bb = 0; bb < 4; ++bb)
        bcol[bb] = (uint32_t)(wn * 8 + (((uint32_t)(bb * 2 + chh)) ^ xb)) * 16;
    uint32_t boff[4];
#pragma unroll
    for (int ks = 0; ks < 4; ++ks)
        boff[ks] = (uint32_t)(ks * 16 + lane_r) * 256;

    float accM[2][8][4];
    int st = 0;
    int iter = start;

    while (iter < end) {
        const int tile  = iter >> 6;
        const int k0    = iter & 63;
        const int tbase = tile << 6;
        const int kend  = min(64, end - tbase);
        const int m0 = (tile >> 5) << 6;    // tiles n-fastest: A panel L2 reuse
        const int n0 = (tile & 31) << 7;

        __syncthreads();   // previous segment's smem reads complete
        // prefill up to 2 stages (NS=3 pipeline)
        {
            int nst = st;
            if (k0 < kend) load_stage(m0, n0, k0, nst);
            CP_COMMIT();
            nst = (nst == NS - 1) ? 0 : nst + 1;
            if (k0 + 1 < kend) load_stage(m0, n0, k0 + 1, nst);
            CP_COMMIT();
        }

#pragma unroll
        for (int t = 0; t < 2; ++t)
#pragma unroll
            for (int nt = 0; nt < 8; ++nt)
#pragma unroll
                for (int i = 0; i < 4; ++i) accM[t][nt][i] = 0.f;

        for (int kt = k0; kt < kend; ++kt) {
            CP_WAIT1();
            __syncthreads();

            const uint32_t Ab = sb + st * STG_BYTES;
            const uint32_t Bb = Ab + 8192;

            int lst = st + 2; if (lst >= NS) lst -= NS;
            if (kt + 2 < kend) load_stage(m0, n0, kt + 2, lst);
            CP_COMMIT();

#pragma unroll
            for (int ks = 0; ks < 4; ++ks) {
                uint32_t af[2][4], bfr[4][4];
#pragma unroll
                for (int t = 0; t < 2; ++t) {
                    uint32_t co = ((uint32_t)(ks * 2 + chh) ^ axr[t]) * 16;
                    ldsm4(af[t], Ab + arow[t] + co);
                }
#pragma unroll
                for (int bb = 0; bb < 4; ++bb)
                    ldsm4t(bfr[bb], Bb + boff[ks] + bcol[bb]);
#pragma unroll
                for (int t = 0; t < 2; ++t)
#pragma unroll
                    for (int nt = 0; nt < 8; ++nt)
                        mma_f16(accM[t][nt], af[t], &bfr[nt >> 1][(nt & 1) * 2]);
            }

            st = (st == NS - 1) ? 0 : st + 1;
        }

        // epilogue for this tile segment
        const bool full = (k0 == 0) && (kend == 64);
#pragma unroll
        for (int t = 0; t < 2; ++t) {
            int row0 = m0 + wm * 32 + t * 16 + (lane >> 2);
#pragma unroll
            for (int nt = 0; nt < 8; ++nt) {
                int col = n0 + wn * 64 + nt * 8 + (lane & 3) * 2;
                float2 b = *(const float2*)(bias + col);
                float a0 = accM[t][nt][0], a1 = accM[t][nt][1];
                float a2 = accM[t][nt][2], a3 = accM[t][nt][3];
                if (full) {
                    float2 o0, o1;
                    o0.x = a0 + b.x;  o0.y = a1 + b.y;
                    o1.x = a2 + b.x;  o1.y = a3 + b.y;
                    *(float2*)(C + (size_t)row0 * NNV + col)       = o0;
                    *(float2*)(C + (size_t)(row0 + 8) * NNV + col) = o1;
                } else {
                    if (k0 == 0) { a0 += b.x; a1 += b.y; a2 += b.x; a3 += b.y; }
                    atomicAdd(C + (size_t)row0 * NNV + col,           a0);
                    atomicAdd(C + (size_t)row0 * NNV + col + 1,       a1);
                    atomicAdd(C + (size_t)(row0 + 8) * NNV + col,     a2);
                    atomicAdd(C + (size_t)(row0 + 8) * NNV + col + 1, a3);
                }
            }
        }

        iter = tbase + kend;
    }
}

// ---------------------------------------------------------------------------
// Host. Inputs: x, scales, zero_points, bias, qweight
// ---------------------------------------------------------------------------
extern "C" void kernel_launch(void* const* d_in, const int* in_sizes, int n_in,
                              void* d_out, int out_size)
{
    const float* x      = (const float*)d_in[0];
    const float* scales = (const float*)d_in[1];
    const float* zp     = (const float*)d_in[2];
    const float* bias   = (const float*)d_in[3];
    const int*   qw     = (const int*)d_in[4];
    float*       out    = (float*)d_out;

    // zero C for atomic partial accumulation (async memset: graph-capturable)
    cudaMemsetAsync(out, 0, (size_t)MMV * NNV * sizeof(float));

    prep_kernel<<<12288, 256>>>((const float4*)x, qw, zp, scales);

    static int grid = 0;
    if (!grid) {
        int sm = 0;
        cudaDeviceGetAttribute(&sm, cudaDevAttrMultiProcessorCount, 0);
        grid = (sm > 0 ? sm : 148) * 3;
        cudaFuncSetAttribute(gemm_kernel, cudaFuncAttributeMaxDynamicSharedMemorySize, SMEM_TOTAL);
    }
    int q = TOT_ITERS / grid, r = TOT_ITERS % grid;
    gemm_kernel<<<grid, 128, SMEM_TOTAL>>>(bias, out, q, r);
}